// round 7
// baseline (speedup 1.0000x reference)
#include <cuda_runtime.h>

#define BB 4
#define HH 16
#define SS 4096
#define DD 64
#define NBH (BB*HH)
#define NCHUNK 8
#define EPS 1e-6f

__device__ float g_kv[NBH * DD * DD];             // [bh][d][f] (final)
__device__ float g_kvp[NCHUNK * NBH * DD * DD];   // per-chunk partials (8MB)
__device__ float g_ksum[NBH * DD];                // [bh][d]
__device__ int   g_mask_fmt;                      // 0 = 4-byte elems, 1 = 1-byte

typedef unsigned long long ull;

// ---------- helpers ----------
__device__ __forceinline__ float fmap(float x) {
    return x > 0.0f ? x + 1.0f : __expf(x);
}

__device__ __forceinline__ void fma2(ull &acc, ull a, ull b) {
    asm("fma.rn.f32x2 %0, %1, %2, %0;" : "+l"(acc) : "l"(a), "l"(b));
}

__device__ __forceinline__ float2 unpackf2(ull v) {
    float2 r;
    asm("mov.b64 {%0, %1}, %2;" : "=f"(r.x), "=f"(r.y) : "l"(v));
    return r;
}

__device__ __forceinline__ float get_valid(const void* mask, int fmt, int idx) {
    if (fmt) return ((const unsigned char*)mask)[idx] == 0 ? 1.0f : 0.0f;
    return ((const unsigned int*)mask)[idx] == 0u ? 1.0f : 0.0f;
}

// ---------- small kernels ----------
__global__ void zero_kernel() {
    int idx = blockIdx.x * blockDim.x + threadIdx.x;
    if (idx < NBH * DD) g_ksum[idx] = 0.0f;
    if (idx == 0)       g_mask_fmt = 0;
}

__global__ void detect_kernel(const unsigned int* __restrict__ mask) {
    int idx = blockIdx.x * blockDim.x + threadIdx.x;  // 4096 threads
    unsigned int w = mask[idx];
    if (w != 0u && w != 1u && w != 0x3F800000u) atomicOr(&g_mask_fmt, 1);
}

// Sum the NCHUNK partial kv matrices. grid 512 x 128 threads, 1 float4/thread.
__global__ void __launch_bounds__(128)
reduce_kernel() {
    const int gidx = blockIdx.x * 128 + threadIdx.x;   // 0..65535
    const int bh  = gidx >> 10;
    const int pos = gidx & 1023;
    const float4* src = (const float4*)g_kvp;
    float4 s = src[(size_t)bh * 1024 + pos];
#pragma unroll
    for (int c = 1; c < NCHUNK; c++) {
        float4 t = src[(size_t)(c * NBH + bh) * 1024 + pos];
        s.x += t.x; s.y += t.y; s.z += t.z; s.w += t.w;
    }
    ((float4*)(g_kv + bh * DD * DD))[pos] = s;
}

// ---------- Pass 1 ----------
// grid (NCHUNK, 64), 256 threads. Thread (i=tid&15, j=tid>>4) owns disjoint
// tile d = {i+16a} x f = 4j..4j+3. k stored DUPLICATED in smem -> the f32x2
// outer product needs zero register packs.
__global__ void __launch_bounds__(256)
pass1_kernel(const float* __restrict__ kk, const float* __restrict__ vv,
             const void* __restrict__ mask) {
    __shared__ float kdup[2][32 * 128];   // [buf][m*128 + 2d] = (k_d, k_d)
    __shared__ float vsh[2][32 * 64];     // [buf][m*64 + f]
    __shared__ float ksbuf[8 * 16 * 4];   // per-warp ksum partials

    const int bh  = blockIdx.y;
    const int s0  = blockIdx.x * 512;
    const int tid = threadIdx.x;
    const int i   = tid & 15;        // d base
    const int j   = tid >> 4;        // f group
    const int fmt = g_mask_fmt;
    const int b   = bh >> 4;

    const float4* kg = (const float4*)(kk + (size_t)bh * SS * DD);
    const float4* vg = (const float4*)(vv + (size_t)bh * SS * DD);

    ull acc[4][2];
#pragma unroll
    for (int a = 0; a < 4; a++) { acc[a][0] = 0ull; acc[a][1] = 0ull; }
    float4 ks4 = make_float4(0.f, 0.f, 0.f, 0.f);   // ksum for d=4*(tid&15)..+3

    float4 kr[2], vr[2];

    // prefetch stage 0
#pragma unroll
    for (int it = 0; it < 2; it++) {
        int vi = it * 256 + tid;
        int sl = vi >> 4, c4 = vi & 15;
        float valid = get_valid(mask, fmt, b * SS + s0 + sl);
        float4 k4 = kg[(size_t)(s0 + sl) * 16 + c4];
        vr[it] = vg[(size_t)(s0 + sl) * 16 + c4];
        k4.x = fmap(k4.x) * valid;
        k4.y = fmap(k4.y) * valid;
        k4.z = fmap(k4.z) * valid;
        k4.w = fmap(k4.w) * valid;
        kr[it] = k4;
        ks4.x += k4.x; ks4.y += k4.y; ks4.z += k4.z; ks4.w += k4.w;
    }

    for (int st = 0; st < 16; st++) {
        const int bufi = st & 1;
        // store current stage (k duplicated)
#pragma unroll
        for (int it = 0; it < 2; it++) {
            int vi = it * 256 + tid;
            int sl = vi >> 4, c4 = vi & 15;
            float4 k4 = kr[it];
            float4 a0 = make_float4(k4.x, k4.x, k4.y, k4.y);
            float4 a1 = make_float4(k4.z, k4.z, k4.w, k4.w);
            *(float4*)(kdup[bufi] + sl * 128 + 8 * c4)     = a0;
            *(float4*)(kdup[bufi] + sl * 128 + 8 * c4 + 4) = a1;
            *(float4*)(vsh[bufi]  + sl * 64  + 4 * c4)     = vr[it];
        }
        __syncthreads();

        // prefetch next stage (overlaps with compute)
        if (st < 15) {
            const int sbase = s0 + (st + 1) * 32;
#pragma unroll
            for (int it = 0; it < 2; it++) {
                int vi = it * 256 + tid;
                int sl = vi >> 4, c4 = vi & 15;
                float valid = get_valid(mask, fmt, b * SS + sbase + sl);
                float4 k4 = kg[(size_t)(sbase + sl) * 16 + c4];
                vr[it] = vg[(size_t)(sbase + sl) * 16 + c4];
                k4.x = fmap(k4.x) * valid;
                k4.y = fmap(k4.y) * valid;
                k4.z = fmap(k4.z) * valid;
                k4.w = fmap(k4.w) * valid;
                kr[it] = k4;
                ks4.x += k4.x; ks4.y += k4.y; ks4.z += k4.z; ks4.w += k4.w;
            }
        }

        // compute 32 tokens — pure LDS + FMA2, no packs
        const float* kb = kdup[bufi];
        const float* vb = vsh[bufi];
#pragma unroll 8
        for (int m = 0; m < 32; m++) {
            ull k0 = *(const ull*)(kb + m * 128 + 2 * i);
            ull k1 = *(const ull*)(kb + m * 128 + 2 * i + 32);
            ull k2 = *(const ull*)(kb + m * 128 + 2 * i + 64);
            ull k3 = *(const ull*)(kb + m * 128 + 2 * i + 96);
            ulonglong2 vd = *(const ulonglong2*)(vb + m * 64 + 4 * j);
            fma2(acc[0][0], k0, vd.x); fma2(acc[0][1], k0, vd.y);
            fma2(acc[1][0], k1, vd.x); fma2(acc[1][1], k1, vd.y);
            fma2(acc[2][0], k2, vd.x); fma2(acc[2][1], k2, vd.y);
            fma2(acc[3][0], k3, vd.x); fma2(acc[3][1], k3, vd.y);
        }
        // no trailing sync needed: next stage writes the other buffer
    }

    // store partial kv tile (disjoint per thread)
    float* dst = g_kvp + (size_t)(blockIdx.x * NBH + bh) * DD * DD;
#pragma unroll
    for (int a = 0; a < 4; a++) {
        float2 lo = unpackf2(acc[a][0]);
        float2 hi = unpackf2(acc[a][1]);
        float4 o = make_float4(lo.x, lo.y, hi.x, hi.y);
        *(float4*)(dst + (i + 16 * a) * 64 + 4 * j) = o;
    }

    // ksum reduce: lanes l and l^16 share c4=tid&15
    ks4.x += __shfl_xor_sync(0xffffffffu, ks4.x, 16);
    ks4.y += __shfl_xor_sync(0xffffffffu, ks4.y, 16);
    ks4.z += __shfl_xor_sync(0xffffffffu, ks4.z, 16);
    ks4.w += __shfl_xor_sync(0xffffffffu, ks4.w, 16);
    const int lane = tid & 31, w = tid >> 5;
    __syncthreads();     // done with kdup/vsh reads
    if (lane < 16)
        *(float4*)(ksbuf + (w * 16 + lane) * 4) = ks4;
    __syncthreads();
    if (tid < 64) {
        const int c4 = tid & 15, comp = tid >> 4;
        float s = 0.f;
#pragma unroll
        for (int ww = 0; ww < 8; ww++)
            s += ksbuf[(ww * 16 + c4) * 4 + comp];
        atomicAdd(&g_ksum[bh * DD + 4 * c4 + comp], s);
    }
}

// ---------- Pass 2 ----------
// grid (32, 64), 128 threads, 128 tokens/block. f32x2 lanes = TOKEN pairs:
// q transposed [d][t] gives natural pairs; kv duplicated once per block.
// kvdup processed in two 32-row halves to keep smem at ~50KB.
__global__ void __launch_bounds__(128)
pass2_kernel(const float* __restrict__ qq, float* __restrict__ out) {
    __shared__ float qsh[64 * 128];     // [d][t]
    __shared__ float kvdup[32 * 128];   // [drel][2f] = (kv, kv)
    __shared__ float kss[64];
    __shared__ float zsh[128];

    const int bh  = blockIdx.y;
    const int t0  = blockIdx.x * 128;
    const int tid = threadIdx.x;

    if (tid < 16)
        ((float4*)kss)[tid] = ((const float4*)(g_ksum + bh * DD))[tid];

    // build kvdup half 0 (d = 0..31)
    const float4* kvg = (const float4*)(g_kv + bh * DD * DD);
#pragma unroll
    for (int it = 0; it < 4; it++) {
        int idx = it * 128 + tid;          // float4 idx in 32x64
        int dr = idx >> 4, c = idx & 15;
        float4 x = kvg[idx];
        *(float4*)(kvdup + dr * 128 + 8 * c)     = make_float4(x.x, x.x, x.y, x.y);
        *(float4*)(kvdup + dr * 128 + 8 * c + 4) = make_float4(x.z, x.z, x.w, x.w);
    }

    // load q (token = tid), feature map
    const float4* qg = (const float4*)(qq + (size_t)bh * SS * DD + (size_t)t0 * DD);
    float4 qr[16];
#pragma unroll
    for (int c = 0; c < 16; c++) {
        float4 x = qg[tid * 16 + c];
        x.x = fmap(x.x); x.y = fmap(x.y); x.z = fmap(x.z); x.w = fmap(x.w);
        qr[c] = x;
    }
    __syncthreads();   // kss ready

    float z = EPS;
#pragma unroll
    for (int c = 0; c < 16; c++) {
        z += qr[c].x * kss[4 * c] + qr[c].y * kss[4 * c + 1]
           + qr[c].z * kss[4 * c + 2] + qr[c].w * kss[4 * c + 3];
    }
    zsh[tid] = 1.0f / z;

    // store q transposed [d][t]
#pragma unroll
    for (int c = 0; c < 16; c++) {
        qsh[(4 * c + 0) * 128 + tid] = qr[c].x;
        qsh[(4 * c + 1) * 128 + tid] = qr[c].y;
        qsh[(4 * c + 2) * 128 + tid] = qr[c].z;
        qsh[(4 * c + 3) * 128 + tid] = qr[c].w;
    }
    __syncthreads();   // qsh, zsh, kvdup(half0) ready

    const int ty = tid >> 3;   // tokens 8ty..8ty+7 (4 pairs)
    const int tx = tid & 7;    // f = 8tx..8tx+7

    ull acc[4][8];
#pragma unroll
    for (int p = 0; p < 4; p++)
#pragma unroll
        for (int f = 0; f < 8; f++) acc[p][f] = 0ull;

#pragma unroll
    for (int half = 0; half < 2; half++) {
        if (half == 1) {
            __syncthreads();   // everyone done reading kvdup half0
#pragma unroll
            for (int it = 0; it < 4; it++) {
                int idx = it * 128 + tid;
                int dr = idx >> 4, c = idx & 15;
                float4 x = kvg[512 + idx];
                *(float4*)(kvdup + dr * 128 + 8 * c)     = make_float4(x.x, x.x, x.y, x.y);
                *(float4*)(kvdup + dr * 128 + 8 * c + 4) = make_float4(x.z, x.z, x.w, x.w);
            }
            __syncthreads();
        }
        const float* qbase = qsh + half * 32 * 128;
#pragma unroll 4
        for (int dr = 0; dr < 32; dr++) {
            ulonglong2 qa = *(const ulonglong2*)(qbase + dr * 128 + 8 * ty);
            ulonglong2 qb = *(const ulonglong2*)(qbase + dr * 128 + 8 * ty + 4);
            const float* kr = kvdup + dr * 128 + 16 * tx;
            ulonglong2 k0 = *(const ulonglong2*)(kr);
            ulonglong2 k1 = *(const ulonglong2*)(kr + 4);
            ulonglong2 k2 = *(const ulonglong2*)(kr + 8);
            ulonglong2 k3 = *(const ulonglong2*)(kr + 12);
            ull kv8[8] = {k0.x, k0.y, k1.x, k1.y, k2.x, k2.y, k3.x, k3.y};
#pragma unroll
            for (int f = 0; f < 8; f++) {
                fma2(acc[0][f], qa.x, kv8[f]);
                fma2(acc[1][f], qa.y, kv8[f]);
                fma2(acc[2][f], qb.x, kv8[f]);
                fma2(acc[3][f], qb.y, kv8[f]);
            }
        }
    }

    // epilogue: acc lanes = tokens (8ty+2p, 8ty+2p+1)
#pragma unroll
    for (int p = 0; p < 4; p++) {
        const int ta = 8 * ty + 2 * p;
        const int tb = ta + 1;
        const float iza = zsh[ta];
        const float izb = zsh[tb];
        float2 u[8];
#pragma unroll
        for (int f = 0; f < 8; f++) u[f] = unpackf2(acc[p][f]);
        float* oga = out + (size_t)bh * SS * DD + (size_t)(t0 + ta) * DD + 8 * tx;
        float* ogb = out + (size_t)bh * SS * DD + (size_t)(t0 + tb) * DD + 8 * tx;
        float4 a0 = make_float4(u[0].x * iza, u[1].x * iza, u[2].x * iza, u[3].x * iza);
        float4 a1 = make_float4(u[4].x * iza, u[5].x * iza, u[6].x * iza, u[7].x * iza);
        float4 b0 = make_float4(u[0].y * izb, u[1].y * izb, u[2].y * izb, u[3].y * izb);
        float4 b1 = make_float4(u[4].y * izb, u[5].y * izb, u[6].y * izb, u[7].y * izb);
        ((float4*)oga)[0] = a0; ((float4*)oga)[1] = a1;
        ((float4*)ogb)[0] = b0; ((float4*)ogb)[1] = b1;
    }
}

extern "C" void kernel_launch(void* const* d_in, const int* in_sizes, int n_in,
                              void* d_out, int out_size) {
    const float* q = (const float*)d_in[0];
    const float* k = (const float*)d_in[1];
    const float* v = (const float*)d_in[2];
    const void*  m = d_in[3];
    float* out = (float*)d_out;

    zero_kernel<<<16, 256>>>();
    detect_kernel<<<16, 256>>>((const unsigned int*)m);
    pass1_kernel<<<dim3(NCHUNK, NBH), 256>>>(k, v, m);
    reduce_kernel<<<512, 128>>>();
    pass2_kernel<<<dim3(SS / 128, NBH), 128>>>(q, out);
}

// round 8
// speedup vs baseline: 1.4605x; 1.4605x over previous
#include <cuda_runtime.h>

#define BB 4
#define HH 16
#define SS 4096
#define DD 64
#define NBH (BB*HH)
#define NCHUNK 8
#define EPS 1e-6f

__device__ float g_kv[NBH * DD * DD];             // [bh][d][f] (final)
__device__ float g_kvp[NCHUNK * NBH * DD * DD];   // per-chunk partials (8MB)
__device__ float g_ksum[NBH * DD];                // [bh][d]
__device__ int   g_mask_fmt;                      // 0 = 4-byte elems, 1 = 1-byte

typedef unsigned long long ull;

// ---------- helpers ----------
__device__ __forceinline__ float fmap(float x) {
    return x > 0.0f ? x + 1.0f : __expf(x);
}

__device__ __forceinline__ void fma2(ull &acc, ull a, ull b) {
    asm("fma.rn.f32x2 %0, %1, %2, %0;" : "+l"(acc) : "l"(a), "l"(b));
}

__device__ __forceinline__ ull packf2(float x, float y) {
    ull r;
    asm("mov.b64 %0, {%1, %2};" : "=l"(r) : "f"(x), "f"(y));
    return r;
}

__device__ __forceinline__ float2 unpackf2(ull v) {
    float2 r;
    asm("mov.b64 {%0, %1}, %2;" : "=f"(r.x), "=f"(r.y) : "l"(v));
    return r;
}

__device__ __forceinline__ float get_valid(const void* mask, int fmt, int idx) {
    if (fmt) return ((const unsigned char*)mask)[idx] == 0 ? 1.0f : 0.0f;
    return ((const unsigned int*)mask)[idx] == 0u ? 1.0f : 0.0f;
}

// ---------- small kernels ----------
__global__ void zero_kernel() {
    int idx = blockIdx.x * blockDim.x + threadIdx.x;
    if (idx < NBH * DD) g_ksum[idx] = 0.0f;
    if (idx == 0)       g_mask_fmt = 0;
}

__global__ void detect_kernel(const unsigned int* __restrict__ mask) {
    int idx = blockIdx.x * blockDim.x + threadIdx.x;  // 4096 threads
    unsigned int w = mask[idx];
    if (w != 0u && w != 1u && w != 0x3F800000u) atomicOr(&g_mask_fmt, 1);
}

// Sum the NCHUNK partial kv matrices. grid 512 x 128 threads, 1 float4/thread.
__global__ void __launch_bounds__(128)
reduce_kernel() {
    const int gidx = blockIdx.x * 128 + threadIdx.x;   // 0..65535
    const int bh  = gidx >> 10;
    const int pos = gidx & 1023;
    const float4* src = (const float4*)g_kvp;
    float4 s = src[(size_t)bh * 1024 + pos];
#pragma unroll
    for (int c = 1; c < NCHUNK; c++) {
        float4 t = src[(size_t)(c * NBH + bh) * 1024 + pos];
        s.x += t.x; s.y += t.y; s.z += t.z; s.w += t.w;
    }
    ((float4*)(g_kv + bh * DD * DD))[pos] = s;
}

// ---------- Pass 1 ---------- (R7 design: pack-free via duplicated k in smem)
// grid (NCHUNK, 64), 256 threads. Thread (i=tid&15, j=tid>>4) owns disjoint
// tile d = {i+16a} x f = 4j..4j+3.
__global__ void __launch_bounds__(256)
pass1_kernel(const float* __restrict__ kk, const float* __restrict__ vv,
             const void* __restrict__ mask) {
    __shared__ float kdup[2][32 * 128];   // [buf][m*128 + 2d] = (k_d, k_d)
    __shared__ float vsh[2][32 * 64];     // [buf][m*64 + f]
    __shared__ float ksbuf[8 * 16 * 4];   // per-warp ksum partials

    const int bh  = blockIdx.y;
    const int s0  = blockIdx.x * 512;
    const int tid = threadIdx.x;
    const int i   = tid & 15;        // d base
    const int j   = tid >> 4;        // f group
    const int fmt = g_mask_fmt;
    const int b   = bh >> 4;

    const float4* kg = (const float4*)(kk + (size_t)bh * SS * DD);
    const float4* vg = (const float4*)(vv + (size_t)bh * SS * DD);

    ull acc[4][2];
#pragma unroll
    for (int a = 0; a < 4; a++) { acc[a][0] = 0ull; acc[a][1] = 0ull; }
    float4 ks4 = make_float4(0.f, 0.f, 0.f, 0.f);

    float4 kr[2], vr[2];

    // prefetch stage 0
#pragma unroll
    for (int it = 0; it < 2; it++) {
        int vi = it * 256 + tid;
        int sl = vi >> 4, c4 = vi & 15;
        float valid = get_valid(mask, fmt, b * SS + s0 + sl);
        float4 k4 = kg[(size_t)(s0 + sl) * 16 + c4];
        vr[it] = vg[(size_t)(s0 + sl) * 16 + c4];
        k4.x = fmap(k4.x) * valid;
        k4.y = fmap(k4.y) * valid;
        k4.z = fmap(k4.z) * valid;
        k4.w = fmap(k4.w) * valid;
        kr[it] = k4;
        ks4.x += k4.x; ks4.y += k4.y; ks4.z += k4.z; ks4.w += k4.w;
    }

    for (int st = 0; st < 16; st++) {
        const int bufi = st & 1;
#pragma unroll
        for (int it = 0; it < 2; it++) {
            int vi = it * 256 + tid;
            int sl = vi >> 4, c4 = vi & 15;
            float4 k4 = kr[it];
            float4 a0 = make_float4(k4.x, k4.x, k4.y, k4.y);
            float4 a1 = make_float4(k4.z, k4.z, k4.w, k4.w);
            *(float4*)(kdup[bufi] + sl * 128 + 8 * c4)     = a0;
            *(float4*)(kdup[bufi] + sl * 128 + 8 * c4 + 4) = a1;
            *(float4*)(vsh[bufi]  + sl * 64  + 4 * c4)     = vr[it];
        }
        __syncthreads();

        if (st < 15) {
            const int sbase = s0 + (st + 1) * 32;
#pragma unroll
            for (int it = 0; it < 2; it++) {
                int vi = it * 256 + tid;
                int sl = vi >> 4, c4 = vi & 15;
                float valid = get_valid(mask, fmt, b * SS + sbase + sl);
                float4 k4 = kg[(size_t)(sbase + sl) * 16 + c4];
                vr[it] = vg[(size_t)(sbase + sl) * 16 + c4];
                k4.x = fmap(k4.x) * valid;
                k4.y = fmap(k4.y) * valid;
                k4.z = fmap(k4.z) * valid;
                k4.w = fmap(k4.w) * valid;
                kr[it] = k4;
                ks4.x += k4.x; ks4.y += k4.y; ks4.z += k4.z; ks4.w += k4.w;
            }
        }

        const float* kb = kdup[bufi];
        const float* vb = vsh[bufi];
#pragma unroll 8
        for (int m = 0; m < 32; m++) {
            ull k0 = *(const ull*)(kb + m * 128 + 2 * i);
            ull k1 = *(const ull*)(kb + m * 128 + 2 * i + 32);
            ull k2 = *(const ull*)(kb + m * 128 + 2 * i + 64);
            ull k3 = *(const ull*)(kb + m * 128 + 2 * i + 96);
            ulonglong2 vd = *(const ulonglong2*)(vb + m * 64 + 4 * j);
            fma2(acc[0][0], k0, vd.x); fma2(acc[0][1], k0, vd.y);
            fma2(acc[1][0], k1, vd.x); fma2(acc[1][1], k1, vd.y);
            fma2(acc[2][0], k2, vd.x); fma2(acc[2][1], k2, vd.y);
            fma2(acc[3][0], k3, vd.x); fma2(acc[3][1], k3, vd.y);
        }
    }

    float* dst = g_kvp + (size_t)(blockIdx.x * NBH + bh) * DD * DD;
#pragma unroll
    for (int a = 0; a < 4; a++) {
        float2 lo = unpackf2(acc[a][0]);
        float2 hi = unpackf2(acc[a][1]);
        float4 o = make_float4(lo.x, lo.y, hi.x, hi.y);
        *(float4*)(dst + (i + 16 * a) * 64 + 4 * j) = o;
    }

    ks4.x += __shfl_xor_sync(0xffffffffu, ks4.x, 16);
    ks4.y += __shfl_xor_sync(0xffffffffu, ks4.y, 16);
    ks4.z += __shfl_xor_sync(0xffffffffu, ks4.z, 16);
    ks4.w += __shfl_xor_sync(0xffffffffu, ks4.w, 16);
    const int lane = tid & 31, w = tid >> 5;
    __syncthreads();
    if (lane < 16)
        *(float4*)(ksbuf + (w * 16 + lane) * 4) = ks4;
    __syncthreads();
    if (tid < 64) {
        const int c4 = tid & 15, comp = tid >> 4;
        float s = 0.f;
#pragma unroll
        for (int ww = 0; ww < 8; ww++)
            s += ksbuf[(ww * 16 + c4) * 4 + comp];
        atomicAdd(&g_ksum[bh * DD + 4 * c4 + comp], s);
    }
}

// ---------- Pass 2 ---------- (R3 layout, 256 threads for occupancy)
// grid (32, 64), 256 threads, 128 tokens/block, thread tile 4t x 8f.
// Conflict-free: kv loads at 16B lane stride, q loads at 16B lane stride.
__global__ void __launch_bounds__(256)
pass2_kernel(const float* __restrict__ qq, float* __restrict__ out) {
    __shared__ float qsh[64 * 128];   // [d][t]
    __shared__ float kvsh[64 * 64];   // [d][f]
    __shared__ float kss[64];
    __shared__ float psh[256];        // z partials (token, half)

    const int bh  = blockIdx.y;
    const int t0  = blockIdx.x * 128;
    const int tid = threadIdx.x;

    const float4* kvg = (const float4*)(g_kv + bh * DD * DD);
#pragma unroll
    for (int it = 0; it < 4; it++)
        ((float4*)kvsh)[it * 256 + tid] = kvg[it * 256 + tid];
    if (tid < 16)
        ((float4*)kss)[tid] = ((const float4*)(g_ksum + bh * DD))[tid];

    // thread loads half a token row: token tp, d-half h
    const int tp = tid >> 1;
    const int h  = tid & 1;
    const float4* qg = (const float4*)(qq + (size_t)bh * SS * DD + (size_t)t0 * DD);
    float4 qr[8];
#pragma unroll
    for (int c = 0; c < 8; c++) {
        float4 x = qg[tp * 16 + 8 * h + c];
        x.x = fmap(x.x); x.y = fmap(x.y); x.z = fmap(x.z); x.w = fmap(x.w);
        qr[c] = x;
    }
    __syncthreads();   // kss + kvsh visible

    // z partial over this thread's 32 d
    float z = 0.0f;
#pragma unroll
    for (int c = 0; c < 8; c++) {
        const int db = 4 * (8 * h + c);
        z += qr[c].x * kss[db]     + qr[c].y * kss[db + 1]
           + qr[c].z * kss[db + 2] + qr[c].w * kss[db + 3];
    }
    psh[tid] = z;

    // transpose into qsh[d][t]
#pragma unroll
    for (int c = 0; c < 8; c++) {
        const int cg = 8 * h + c;
        qsh[(4 * cg + 0) * 128 + tp] = qr[c].x;
        qsh[(4 * cg + 1) * 128 + tp] = qr[c].y;
        qsh[(4 * cg + 2) * 128 + tp] = qr[c].z;
        qsh[(4 * cg + 3) * 128 + tp] = qr[c].w;
    }
    __syncthreads();   // qsh + psh visible

    const int ty = tid >> 3;   // 0..31 -> tokens 4ty..4ty+3
    const int tx = tid & 7;    // f: 4tx..4tx+3, 32+4tx..32+4tx+3

    ull acc[4][4];
#pragma unroll
    for (int r = 0; r < 4; r++)
#pragma unroll
        for (int p = 0; p < 4; p++) acc[r][p] = 0ull;

#pragma unroll 4
    for (int d = 0; d < 64; d++) {
        float4 qa = *(const float4*)(qsh + d * 128 + 4 * ty);
        ulonglong2 va = *(const ulonglong2*)(kvsh + d * 64 + 4 * tx);
        ulonglong2 vb = *(const ulonglong2*)(kvsh + d * 64 + 32 + 4 * tx);
        float qs[4] = {qa.x, qa.y, qa.z, qa.w};
#pragma unroll
        for (int r = 0; r < 4; r++) {
            ull qp = packf2(qs[r], qs[r]);
            fma2(acc[r][0], qp, va.x);
            fma2(acc[r][1], qp, va.y);
            fma2(acc[r][2], qp, vb.x);
            fma2(acc[r][3], qp, vb.y);
        }
    }

#pragma unroll
    for (int r = 0; r < 4; r++) {
        const int t = 4 * ty + r;
        const float invz = 1.0f / (psh[2 * t] + psh[2 * t + 1] + EPS);
        float* og = out + (size_t)bh * SS * DD + (size_t)(t0 + t) * DD;
        float2 a0 = unpackf2(acc[r][0]);
        float2 a1 = unpackf2(acc[r][1]);
        float2 a2 = unpackf2(acc[r][2]);
        float2 a3 = unpackf2(acc[r][3]);
        float4 o0 = make_float4(a0.x * invz, a0.y * invz, a1.x * invz, a1.y * invz);
        float4 o1 = make_float4(a2.x * invz, a2.y * invz, a3.x * invz, a3.y * invz);
        *(float4*)(og + 4 * tx)      = o0;
        *(float4*)(og + 32 + 4 * tx) = o1;
    }
}

extern "C" void kernel_launch(void* const* d_in, const int* in_sizes, int n_in,
                              void* d_out, int out_size) {
    const float* q = (const float*)d_in[0];
    const float* k = (const float*)d_in[1];
    const float* v = (const float*)d_in[2];
    const void*  m = d_in[3];
    float* out = (float*)d_out;

    zero_kernel<<<16, 256>>>();
    detect_kernel<<<16, 256>>>((const unsigned int*)m);
    pass1_kernel<<<dim3(NCHUNK, NBH), 256>>>(k, v, m);
    reduce_kernel<<<512, 128>>>();
    pass2_kernel<<<dim3(SS / 128, NBH), 256>>>(q, out);
}

// round 9
// speedup vs baseline: 1.7450x; 1.1948x over previous
#include <cuda_runtime.h>

#define BB 4
#define HH 16
#define SS 4096
#define DD 64
#define NBH (BB*HH)
#define NCHUNK 8
#define EPS 1e-6f

__device__ float g_kv[NBH * DD * DD];             // [bh][d][f] (final)
__device__ float g_kvp[NCHUNK * NBH * DD * DD];   // per-chunk partials (8MB)
__device__ float g_ksum[NBH * DD];                // [bh][d]
__device__ int   g_mask_fmt;                      // 0 = 4-byte elems, 1 = 1-byte

typedef unsigned long long ull;

// ---------- helpers ----------
__device__ __forceinline__ float fmap(float x) {
    return x > 0.0f ? x + 1.0f : __expf(x);
}

__device__ __forceinline__ void fma2(ull &acc, ull a, ull b) {
    asm("fma.rn.f32x2 %0, %1, %2, %0;" : "+l"(acc) : "l"(a), "l"(b));
}

__device__ __forceinline__ ull packf2(float x, float y) {
    ull r;
    asm("mov.b64 %0, {%1, %2};" : "=l"(r) : "f"(x), "f"(y));
    return r;
}

__device__ __forceinline__ float2 unpackf2(ull v) {
    float2 r;
    asm("mov.b64 {%0, %1}, %2;" : "=f"(r.x), "=f"(r.y) : "l"(v));
    return r;
}

__device__ __forceinline__ float get_valid(const void* mask, int fmt, int idx) {
    if (fmt) return ((const unsigned char*)mask)[idx] == 0 ? 1.0f : 0.0f;
    return ((const unsigned int*)mask)[idx] == 0u ? 1.0f : 0.0f;
}

// ---------- small kernels ----------
__global__ void zero_kernel() {
    int idx = blockIdx.x * blockDim.x + threadIdx.x;
    if (idx < NBH * DD) g_ksum[idx] = 0.0f;
    if (idx == 0)       g_mask_fmt = 0;
}

__global__ void detect_kernel(const unsigned int* __restrict__ mask) {
    int idx = blockIdx.x * blockDim.x + threadIdx.x;  // 4096 threads
    unsigned int w = mask[idx];
    if (w != 0u && w != 1u && w != 0x3F800000u) atomicOr(&g_mask_fmt, 1);
}

// Sum the NCHUNK partial kv matrices. grid 512 x 128 threads, 1 float4/thread.
__global__ void __launch_bounds__(128)
reduce_kernel() {
    const int gidx = blockIdx.x * 128 + threadIdx.x;   // 0..65535
    const int bh  = gidx >> 10;
    const int pos = gidx & 1023;
    const float4* src = (const float4*)g_kvp;
    float4 s = src[(size_t)bh * 1024 + pos];
#pragma unroll
    for (int c = 1; c < NCHUNK; c++) {
        float4 t = src[(size_t)(c * NBH + bh) * 1024 + pos];
        s.x += t.x; s.y += t.y; s.z += t.z; s.w += t.w;
    }
    ((float4*)(g_kv + bh * DD * DD))[pos] = s;
}

// ---------- Pass 1 ----------
// grid (NCHUNK, 64), 256 threads. Thread (i=tid&31, j=tid>>5): disjoint tile
// d = {2i, 2i+1} x f = 8j..8j+7. k stored PAIR-DUPLICATED in smem:
// kdup[m][4i..4i+3] = (k_2i, k_2i, k_2i+1, k_2i+1) -> one conflict-free
// LDS.128 yields both FMA2 multiplier pairs. v reads are warp-broadcast.
// 16-token stages, double-buffered, 24KB smem total.
__global__ void __launch_bounds__(256)
pass1_kernel(const float* __restrict__ kk, const float* __restrict__ vv,
             const void* __restrict__ mask) {
    __shared__ float kdup[2][16 * 128];   // 16KB
    __shared__ float vsh[2][16 * 64];     // 8KB

    const int bh  = blockIdx.y;
    const int s0  = blockIdx.x * 512;
    const int tid = threadIdx.x;
    const int i   = tid & 31;        // d pair index (warp lane)
    const int j   = tid >> 5;        // f octet (warp id)
    const int fmt = g_mask_fmt;
    const int b   = bh >> 4;

    const float4* kg = (const float4*)(kk + (size_t)bh * SS * DD);
    const float4* vg = (const float4*)(vv + (size_t)bh * SS * DD);

    ull acc[2][4];
#pragma unroll
    for (int a = 0; a < 2; a++)
#pragma unroll
        for (int p = 0; p < 4; p++) acc[a][p] = 0ull;
    float ks0 = 0.f, ks1 = 0.f;      // ksum for d=2i, 2i+1 (used by warp 0)

    // loader mapping: thread -> (token sl = tid>>4, col c4 = tid&15)
    const int sl = tid >> 4;
    const int c4 = tid & 15;

    float4 kr, vr;
    {
        float valid = get_valid(mask, fmt, b * SS + s0 + sl);
        float4 k4 = kg[(size_t)(s0 + sl) * 16 + c4];
        vr = vg[(size_t)(s0 + sl) * 16 + c4];
        k4.x = fmap(k4.x) * valid;
        k4.y = fmap(k4.y) * valid;
        k4.z = fmap(k4.z) * valid;
        k4.w = fmap(k4.w) * valid;
        kr = k4;
    }

    for (int st = 0; st < 32; st++) {
        const int bufi = st & 1;
        // store current stage: k duplicated, v natural
        {
            float4 a0 = make_float4(kr.x, kr.x, kr.y, kr.y);
            float4 a1 = make_float4(kr.z, kr.z, kr.w, kr.w);
            *(float4*)(kdup[bufi] + sl * 128 + 8 * c4)     = a0;
            *(float4*)(kdup[bufi] + sl * 128 + 8 * c4 + 4) = a1;
            *(float4*)(vsh[bufi]  + sl * 64  + 4 * c4)     = vr;
        }
        __syncthreads();

        // prefetch next stage (overlaps compute)
        if (st < 31) {
            const int sbase = s0 + (st + 1) * 16;
            float valid = get_valid(mask, fmt, b * SS + sbase + sl);
            float4 k4 = kg[(size_t)(sbase + sl) * 16 + c4];
            vr = vg[(size_t)(sbase + sl) * 16 + c4];
            k4.x = fmap(k4.x) * valid;
            k4.y = fmap(k4.y) * valid;
            k4.z = fmap(k4.z) * valid;
            k4.w = fmap(k4.w) * valid;
            kr = k4;
        }

        // compute 16 tokens: 1 LDS.128 (kdup) + 2 broadcast LDS.128 (v) + 8 FMA2
        const float* kb = kdup[bufi];
        const float* vb = vsh[bufi];
#pragma unroll
        for (int m = 0; m < 16; m++) {
            ulonglong2 kp = *(const ulonglong2*)(kb + m * 128 + 4 * i);
            ulonglong2 va = *(const ulonglong2*)(vb + m * 64 + 8 * j);
            ulonglong2 vc = *(const ulonglong2*)(vb + m * 64 + 8 * j + 4);
            fma2(acc[0][0], kp.x, va.x); fma2(acc[0][1], kp.x, va.y);
            fma2(acc[0][2], kp.x, vc.x); fma2(acc[0][3], kp.x, vc.y);
            fma2(acc[1][0], kp.y, va.x); fma2(acc[1][1], kp.y, va.y);
            fma2(acc[1][2], kp.y, vc.x); fma2(acc[1][3], kp.y, vc.y);
            if (j == 0) {
                float2 kf = unpackf2(kp.x);
                float2 kg2 = unpackf2(kp.y);
                ks0 += kf.x; ks1 += kg2.x;
            }
        }
        // no trailing sync: passing the next iteration's barrier implies all
        // warps finished this buffer's compute before it is overwritten.
    }

    // store partial kv tile: rows d=2i, 2i+1, cols f=8j..8j+7
    float* dst = g_kvp + (size_t)(blockIdx.x * NBH + bh) * DD * DD;
#pragma unroll
    for (int a = 0; a < 2; a++) {
        float2 u0 = unpackf2(acc[a][0]);
        float2 u1 = unpackf2(acc[a][1]);
        float2 u2 = unpackf2(acc[a][2]);
        float2 u3 = unpackf2(acc[a][3]);
        float* row = dst + (2 * i + a) * 64 + 8 * j;
        *(float4*)(row)     = make_float4(u0.x, u0.y, u1.x, u1.y);
        *(float4*)(row + 4) = make_float4(u2.x, u2.y, u3.x, u3.y);
    }
    if (j == 0) {
        atomicAdd(&g_ksum[bh * DD + 2 * i],     ks0);
        atomicAdd(&g_ksum[bh * DD + 2 * i + 1], ks1);
    }
}

// ---------- Pass 2 ---------- (R3/R6 winner, verbatim)
// grid (32, 64), 128 threads, 128 tokens/block, thread tile 8t x 8f.
__global__ void __launch_bounds__(128)
pass2_kernel(const float* __restrict__ qq, float* __restrict__ out) {
    __shared__ float qsh[64 * 128];   // [d][t]
    __shared__ float kvsh[64 * 64];   // [d][f]
    __shared__ float kss[64];
    __shared__ float zsh[128];

    const int bh  = blockIdx.y;
    const int t0  = blockIdx.x * 128;
    const int tid = threadIdx.x;

    const float4* kvg = (const float4*)(g_kv + bh * DD * DD);
#pragma unroll
    for (int it = 0; it < 8; it++)
        ((float4*)kvsh)[it * 128 + tid] = kvg[it * 128 + tid];
    if (tid < 16)
        ((float4*)kss)[tid] = ((const float4*)(g_ksum + bh * DD))[tid];

    const float4* qg = (const float4*)(qq + (size_t)bh * SS * DD + (size_t)t0 * DD);
    float4 qr[16];
#pragma unroll
    for (int c = 0; c < 16; c++) {
        float4 x = qg[tid * 16 + c];
        x.x = fmap(x.x); x.y = fmap(x.y); x.z = fmap(x.z); x.w = fmap(x.w);
        qr[c] = x;
    }
    __syncthreads();

    float z = EPS;
#pragma unroll
    for (int c = 0; c < 16; c++) {
        z += qr[c].x * kss[4 * c] + qr[c].y * kss[4 * c + 1]
           + qr[c].z * kss[4 * c + 2] + qr[c].w * kss[4 * c + 3];
    }
    zsh[tid] = 1.0f / z;

#pragma unroll
    for (int c = 0; c < 16; c++) {
        qsh[(4 * c + 0) * 128 + tid] = qr[c].x;
        qsh[(4 * c + 1) * 128 + tid] = qr[c].y;
        qsh[(4 * c + 2) * 128 + tid] = qr[c].z;
        qsh[(4 * c + 3) * 128 + tid] = qr[c].w;
    }
    __syncthreads();

    const int ty = tid >> 3;   // 0..15
    const int tx = tid & 7;    // 0..7

    ull acc[8][4];
#pragma unroll
    for (int r = 0; r < 8; r++)
#pragma unroll
        for (int p = 0; p < 4; p++) acc[r][p] = 0ull;

#pragma unroll 4
    for (int d = 0; d < 64; d++) {
        float4 qa = *(const float4*)(qsh + d * 128 + 4 * ty);
        float4 qb = *(const float4*)(qsh + d * 128 + 64 + 4 * ty);
        ulonglong2 va = *(const ulonglong2*)(kvsh + d * 64 + 4 * tx);
        ulonglong2 vb = *(const ulonglong2*)(kvsh + d * 64 + 32 + 4 * tx);
        float qs[8] = {qa.x, qa.y, qa.z, qa.w, qb.x, qb.y, qb.z, qb.w};
#pragma unroll
        for (int r = 0; r < 8; r++) {
            ull qp = packf2(qs[r], qs[r]);
            fma2(acc[r][0], qp, va.x);
            fma2(acc[r][1], qp, va.y);
            fma2(acc[r][2], qp, vb.x);
            fma2(acc[r][3], qp, vb.y);
        }
    }

#pragma unroll
    for (int r = 0; r < 8; r++) {
        const int t = (r < 4) ? (4 * ty + r) : (64 + 4 * ty + r - 4);
        const float invz = zsh[t];
        float* og = out + (size_t)bh * SS * DD + (size_t)(t0 + t) * DD;
        float2 a0 = unpackf2(acc[r][0]);
        float2 a1 = unpackf2(acc[r][1]);
        float2 a2 = unpackf2(acc[r][2]);
        float2 a3 = unpackf2(acc[r][3]);
        float4 o0 = make_float4(a0.x * invz, a0.y * invz, a1.x * invz, a1.y * invz);
        float4 o1 = make_float4(a2.x * invz, a2.y * invz, a3.x * invz, a3.y * invz);
        *(float4*)(og + 4 * tx)      = o0;
        *(float4*)(og + 32 + 4 * tx) = o1;
    }
}

extern "C" void kernel_launch(void* const* d_in, const int* in_sizes, int n_in,
                              void* d_out, int out_size) {
    const float* q = (const float*)d_in[0];
    const float* k = (const float*)d_in[1];
    const float* v = (const float*)d_in[2];
    const void*  m = d_in[3];
    float* out = (float*)d_out;

    zero_kernel<<<16, 256>>>();
    detect_kernel<<<16, 256>>>((const unsigned int*)m);
    pass1_kernel<<<dim3(NCHUNK, NBH), 256>>>(k, v, m);
    reduce_kernel<<<512, 128>>>();
    pass2_kernel<<<dim3(SS / 128, NBH), 128>>>(q, out);
}

// round 10
// speedup vs baseline: 2.0147x; 1.1546x over previous
#include <cuda_runtime.h>

#define BB 4
#define HH 16
#define SS 4096
#define DD 64
#define NBH (BB*HH)
#define NCHUNK 8
#define EPS 1e-6f

__device__ float g_kv[NBH * DD * DD];             // [bh][d][f] (final)
__device__ float g_kvp[NCHUNK * NBH * DD * DD];   // per-chunk partials (8MB)
__device__ float g_ksum[NBH * DD];                // [bh][d]
__device__ int   g_mask_fmt;                      // 0 = 4-byte elems, 1 = 1-byte

typedef unsigned long long ull;

// ---------- helpers ----------
__device__ __forceinline__ float fmap(float x) {
    return x > 0.0f ? x + 1.0f : __expf(x);
}

__device__ __forceinline__ void fma2(ull &acc, ull a, ull b) {
    asm("fma.rn.f32x2 %0, %1, %2, %0;" : "+l"(acc) : "l"(a), "l"(b));
}

__device__ __forceinline__ ull packf2(float x, float y) {
    ull r;
    asm("mov.b64 %0, {%1, %2};" : "=l"(r) : "f"(x), "f"(y));
    return r;
}

__device__ __forceinline__ float2 unpackf2(ull v) {
    float2 r;
    asm("mov.b64 {%0, %1}, %2;" : "=f"(r.x), "=f"(r.y) : "l"(v));
    return r;
}

__device__ __forceinline__ float get_valid(const void* mask, int fmt, int idx) {
    if (fmt) return ((const unsigned char*)mask)[idx] == 0 ? 1.0f : 0.0f;
    return ((const unsigned int*)mask)[idx] == 0u ? 1.0f : 0.0f;
}

// ---------- small kernels ----------
__global__ void zero_kernel() {
    int idx = blockIdx.x * blockDim.x + threadIdx.x;
    if (idx < NBH * DD) g_ksum[idx] = 0.0f;
    if (idx == 0)       g_mask_fmt = 0;
}

__global__ void detect_kernel(const unsigned int* __restrict__ mask) {
    int idx = blockIdx.x * blockDim.x + threadIdx.x;  // 4096 threads
    unsigned int w = mask[idx];
    if (w != 0u && w != 1u && w != 0x3F800000u) atomicOr(&g_mask_fmt, 1);
}

// Sum the NCHUNK partial kv matrices. grid 512 x 128 threads, 1 float4/thread.
__global__ void __launch_bounds__(128)
reduce_kernel() {
    const int gidx = blockIdx.x * 128 + threadIdx.x;   // 0..65535
    const int bh  = gidx >> 10;
    const int pos = gidx & 1023;
    const float4* src = (const float4*)g_kvp;
    float4 s = src[(size_t)bh * 1024 + pos];
#pragma unroll
    for (int c = 1; c < NCHUNK; c++) {
        float4 t = src[(size_t)(c * NBH + bh) * 1024 + pos];
        s.x += t.x; s.y += t.y; s.z += t.z; s.w += t.w;
    }
    ((float4*)(g_kv + bh * DD * DD))[pos] = s;
}

// ---------- Pass 1 ---------- (R6 structure; ksum moved to loader side)
// grid (NCHUNK, 64), 256 threads. Thread (i=tid&15, j=tid>>4) owns the
// DISJOINT tile d=4i..4i+3 x f=4j..4j+3; every thread visits every token.
// Register-staged double-buffered smem, one __syncthreads per 32-token stage.
__global__ void __launch_bounds__(256)
pass1_kernel(const float* __restrict__ kk, const float* __restrict__ vv,
             const void* __restrict__ mask) {
    __shared__ float ksh[2][2048];
    __shared__ float vsh[2][2048];
    __shared__ float ksbuf[8 * 16 * 4];   // per-warp ksum partials

    const int bh  = blockIdx.y;
    const int s0  = blockIdx.x * 512;
    const int tid = threadIdx.x;
    const int i   = tid & 15;        // d group
    const int j   = tid >> 4;        // f group
    const int fmt = g_mask_fmt;
    const int b   = bh >> 4;

    const float4* kg = (const float4*)(kk + (size_t)bh * SS * DD);
    const float4* vg = (const float4*)(vv + (size_t)bh * SS * DD);

    ull acc[4][2];
#pragma unroll
    for (int a = 0; a < 4; a++) { acc[a][0] = 0ull; acc[a][1] = 0ull; }
    // loader-side ksum for d = 4*(tid&15) .. +3 (c4 = tid&15 on loads)
    float4 ks4 = make_float4(0.f, 0.f, 0.f, 0.f);

    float4 kr[2], vr[2];

    // prefetch stage 0
#pragma unroll
    for (int it = 0; it < 2; it++) {
        int vi = it * 256 + tid;
        int sl = vi >> 4, c4 = vi & 15;
        float valid = get_valid(mask, fmt, b * SS + s0 + sl);
        float4 k4 = kg[(size_t)(s0 + sl) * 16 + c4];
        vr[it] = vg[(size_t)(s0 + sl) * 16 + c4];
        k4.x = fmap(k4.x) * valid;
        k4.y = fmap(k4.y) * valid;
        k4.z = fmap(k4.z) * valid;
        k4.w = fmap(k4.w) * valid;
        kr[it] = k4;
        ks4.x += k4.x; ks4.y += k4.y; ks4.z += k4.z; ks4.w += k4.w;
    }

    for (int st = 0; st < 16; st++) {
        const int bufi = st & 1;
        // store current stage regs -> smem
#pragma unroll
        for (int it = 0; it < 2; it++) {
            ((float4*)ksh[bufi])[it * 256 + tid] = kr[it];
            ((float4*)vsh[bufi])[it * 256 + tid] = vr[it];
        }
        __syncthreads();

        // prefetch next stage (overlaps with compute below)
        if (st < 15) {
            const int sbase = s0 + (st + 1) * 32;
#pragma unroll
            for (int it = 0; it < 2; it++) {
                int vi = it * 256 + tid;
                int sl = vi >> 4, c4 = vi & 15;
                float valid = get_valid(mask, fmt, b * SS + sbase + sl);
                float4 k4 = kg[(size_t)(sbase + sl) * 16 + c4];
                vr[it] = vg[(size_t)(sbase + sl) * 16 + c4];
                k4.x = fmap(k4.x) * valid;
                k4.y = fmap(k4.y) * valid;
                k4.z = fmap(k4.z) * valid;
                k4.w = fmap(k4.w) * valid;
                kr[it] = k4;
                ks4.x += k4.x; ks4.y += k4.y; ks4.z += k4.z; ks4.w += k4.w;
            }
        }

        // compute 32 tokens from buf — pure LDS + pack + FMA2
        const float* kb = ksh[bufi];
        const float* vb = vsh[bufi];
#pragma unroll 8
        for (int m = 0; m < 32; m++) {
            float4 kd = *(const float4*)(kb + m * 64 + 4 * i);
            ulonglong2 vd = *(const ulonglong2*)(vb + m * 64 + 4 * j);
            ull p;
            p = packf2(kd.x, kd.x); fma2(acc[0][0], p, vd.x); fma2(acc[0][1], p, vd.y);
            p = packf2(kd.y, kd.y); fma2(acc[1][0], p, vd.x); fma2(acc[1][1], p, vd.y);
            p = packf2(kd.z, kd.z); fma2(acc[2][0], p, vd.x); fma2(acc[2][1], p, vd.y);
            p = packf2(kd.w, kd.w); fma2(acc[3][0], p, vd.x); fma2(acc[3][1], p, vd.y);
        }
        // no trailing sync: next stage writes the other buffer, and passing
        // the next store-sync implies all warps finished this compute.
    }

    // store this block's partial kv tile (disjoint per thread — plain stores)
    float* dst = g_kvp + (size_t)(blockIdx.x * NBH + bh) * DD * DD;
#pragma unroll
    for (int a = 0; a < 4; a++) {
        float2 lo = unpackf2(acc[a][0]);
        float2 hi = unpackf2(acc[a][1]);
        float4 o = make_float4(lo.x, lo.y, hi.x, hi.y);
        *(float4*)(dst + (4 * i + a) * 64 + 4 * j) = o;
    }

    // ksum reduce: lanes l and l^16 hold the same c4 column group
    ks4.x += __shfl_xor_sync(0xffffffffu, ks4.x, 16);
    ks4.y += __shfl_xor_sync(0xffffffffu, ks4.y, 16);
    ks4.z += __shfl_xor_sync(0xffffffffu, ks4.z, 16);
    ks4.w += __shfl_xor_sync(0xffffffffu, ks4.w, 16);
    const int lane = tid & 31, w = tid >> 5;
    __syncthreads();     // done with ksh/vsh reads
    if (lane < 16)
        *(float4*)(ksbuf + (w * 16 + lane) * 4) = ks4;
    __syncthreads();
    if (tid < 64) {
        const int c4 = tid & 15, comp = tid >> 4;
        float s = 0.f;
#pragma unroll
        for (int ww = 0; ww < 8; ww++)
            s += ksbuf[(ww * 16 + c4) * 4 + comp];
        atomicAdd(&g_ksum[bh * DD + 4 * c4 + comp], s);
    }
}

// ---------- Pass 2 ---------- (R3/R6 winner, verbatim)
// grid (32, 64), 128 threads, 128 tokens/block, thread tile 8t x 8f.
__global__ void __launch_bounds__(128)
pass2_kernel(const float* __restrict__ qq, float* __restrict__ out) {
    __shared__ float qsh[64 * 128];   // [d][t]
    __shared__ float kvsh[64 * 64];   // [d][f]
    __shared__ float kss[64];
    __shared__ float zsh[128];

    const int bh  = blockIdx.y;
    const int t0  = blockIdx.x * 128;
    const int tid = threadIdx.x;

    const float4* kvg = (const float4*)(g_kv + bh * DD * DD);
#pragma unroll
    for (int it = 0; it < 8; it++)
        ((float4*)kvsh)[it * 128 + tid] = kvg[it * 128 + tid];
    if (tid < 16)
        ((float4*)kss)[tid] = ((const float4*)(g_ksum + bh * DD))[tid];

    const float4* qg = (const float4*)(qq + (size_t)bh * SS * DD + (size_t)t0 * DD);
    float4 qr[16];
#pragma unroll
    for (int c = 0; c < 16; c++) {
        float4 x = qg[tid * 16 + c];
        x.x = fmap(x.x); x.y = fmap(x.y); x.z = fmap(x.z); x.w = fmap(x.w);
        qr[c] = x;
    }
    __syncthreads();

    float z = EPS;
#pragma unroll
    for (int c = 0; c < 16; c++) {
        z += qr[c].x * kss[4 * c] + qr[c].y * kss[4 * c + 1]
           + qr[c].z * kss[4 * c + 2] + qr[c].w * kss[4 * c + 3];
    }
    zsh[tid] = 1.0f / z;

#pragma unroll
    for (int c = 0; c < 16; c++) {
        qsh[(4 * c + 0) * 128 + tid] = qr[c].x;
        qsh[(4 * c + 1) * 128 + tid] = qr[c].y;
        qsh[(4 * c + 2) * 128 + tid] = qr[c].z;
        qsh[(4 * c + 3) * 128 + tid] = qr[c].w;
    }
    __syncthreads();

    const int ty = tid >> 3;   // 0..15
    const int tx = tid & 7;    // 0..7

    ull acc[8][4];
#pragma unroll
    for (int r = 0; r < 8; r++)
#pragma unroll
        for (int p = 0; p < 4; p++) acc[r][p] = 0ull;

#pragma unroll 4
    for (int d = 0; d < 64; d++) {
        float4 qa = *(const float4*)(qsh + d * 128 + 4 * ty);
        float4 qb = *(const float4*)(qsh + d * 128 + 64 + 4 * ty);
        ulonglong2 va = *(const ulonglong2*)(kvsh + d * 64 + 4 * tx);
        ulonglong2 vb = *(const ulonglong2*)(kvsh + d * 64 + 32 + 4 * tx);
        float qs[8] = {qa.x, qa.y, qa.z, qa.w, qb.x, qb.y, qb.z, qb.w};
#pragma unroll
        for (int r = 0; r < 8; r++) {
            ull qp = packf2(qs[r], qs[r]);
            fma2(acc[r][0], qp, va.x);
            fma2(acc[r][1], qp, va.y);
            fma2(acc[r][2], qp, vb.x);
            fma2(acc[r][3], qp, vb.y);
        }
    }

#pragma unroll
    for (int r = 0; r < 8; r++) {
        const int t = (r < 4) ? (4 * ty + r) : (64 + 4 * ty + r - 4);
        const float invz = zsh[t];
        float* og = out + (size_t)bh * SS * DD + (size_t)(t0 + t) * DD;
        float2 a0 = unpackf2(acc[r][0]);
        float2 a1 = unpackf2(acc[r][1]);
        float2 a2 = unpackf2(acc[r][2]);
        float2 a3 = unpackf2(acc[r][3]);
        float4 o0 = make_float4(a0.x * invz, a0.y * invz, a1.x * invz, a1.y * invz);
        float4 o1 = make_float4(a2.x * invz, a2.y * invz, a3.x * invz, a3.y * invz);
        *(float4*)(og + 4 * tx)      = o0;
        *(float4*)(og + 32 + 4 * tx) = o1;
    }
}

extern "C" void kernel_launch(void* const* d_in, const int* in_sizes, int n_in,
                              void* d_out, int out_size) {
    const float* q = (const float*)d_in[0];
    const float* k = (const float*)d_in[1];
    const float* v = (const float*)d_in[2];
    const void*  m = d_in[3];
    float* out = (float*)d_out;

    zero_kernel<<<16, 256>>>();
    detect_kernel<<<16, 256>>>((const unsigned int*)m);
    pass1_kernel<<<dim3(NCHUNK, NBH), 256>>>(k, v, m);
    reduce_kernel<<<512, 128>>>();
    pass2_kernel<<<dim3(SS / 128, NBH), 128>>>(q, out);
}

// round 11
// speedup vs baseline: 2.0156x; 1.0004x over previous
#include <cuda_runtime.h>

#define BB 4
#define HH 16
#define SS 4096
#define DD 64
#define NBH (BB*HH)
#define NCHUNK 8
#define EPS 1e-6f

__device__ float g_kv[NBH * DD * DD];             // [bh][d][f] (final)
__device__ float g_kvp[NCHUNK * NBH * DD * DD];   // per-chunk partials (8MB)
__device__ float g_ksum[NBH * DD];                // [bh][d]
__device__ int   g_mask_fmt;                      // 0 = 4-byte elems, 1 = 1-byte

typedef unsigned long long ull;

// ---------- helpers ----------
__device__ __forceinline__ float fmap(float x) {
    return x > 0.0f ? x + 1.0f : __expf(x);
}

__device__ __forceinline__ void fma2(ull &acc, ull a, ull b) {
    asm("fma.rn.f32x2 %0, %1, %2, %0;" : "+l"(acc) : "l"(a), "l"(b));
}

__device__ __forceinline__ ull packf2(float x, float y) {
    ull r;
    asm("mov.b64 %0, {%1, %2};" : "=l"(r) : "f"(x), "f"(y));
    return r;
}

__device__ __forceinline__ float2 unpackf2(ull v) {
    float2 r;
    asm("mov.b64 {%0, %1}, %2;" : "=f"(r.x), "=f"(r.y) : "l"(v));
    return r;
}

__device__ __forceinline__ float get_valid(const void* mask, int fmt, int idx) {
    if (fmt) return ((const unsigned char*)mask)[idx] == 0 ? 1.0f : 0.0f;
    return ((const unsigned int*)mask)[idx] == 0u ? 1.0f : 0.0f;
}

// ---------- small kernels ----------
__global__ void zero_kernel() {
    int idx = blockIdx.x * blockDim.x + threadIdx.x;
    if (idx < NBH * DD) g_ksum[idx] = 0.0f;
    if (idx == 0)       g_mask_fmt = 0;
}

__global__ void detect_kernel(const unsigned int* __restrict__ mask) {
    int idx = blockIdx.x * blockDim.x + threadIdx.x;  // 4096 threads
    unsigned int w = mask[idx];
    if (w != 0u && w != 1u && w != 0x3F800000u) atomicOr(&g_mask_fmt, 1);
}

// Sum the NCHUNK partial kv matrices. grid 512 x 128 threads, 1 float4/thread.
__global__ void __launch_bounds__(128)
reduce_kernel() {
    const int gidx = blockIdx.x * 128 + threadIdx.x;   // 0..65535
    const int bh  = gidx >> 10;
    const int pos = gidx & 1023;
    const float4* src = (const float4*)g_kvp;
    float4 s = src[(size_t)bh * 1024 + pos];
#pragma unroll
    for (int c = 1; c < NCHUNK; c++) {
        float4 t = src[(size_t)(c * NBH + bh) * 1024 + pos];
        s.x += t.x; s.y += t.y; s.z += t.z; s.w += t.w;
    }
    ((float4*)(g_kv + bh * DD * DD))[pos] = s;
}

// ---------- Pass 1 ---------- (R6 structure; ksum moved to loader side)
// grid (NCHUNK, 64), 256 threads. Thread (i=tid&15, j=tid>>4) owns the
// DISJOINT tile d=4i..4i+3 x f=4j..4j+3; every thread visits every token.
// Register-staged double-buffered smem, one __syncthreads per 32-token stage.
__global__ void __launch_bounds__(256)
pass1_kernel(const float* __restrict__ kk, const float* __restrict__ vv,
             const void* __restrict__ mask) {
    __shared__ float ksh[2][2048];
    __shared__ float vsh[2][2048];
    __shared__ float ksbuf[8 * 16 * 4];   // per-warp ksum partials

    const int bh  = blockIdx.y;
    const int s0  = blockIdx.x * 512;
    const int tid = threadIdx.x;
    const int i   = tid & 15;        // d group
    const int j   = tid >> 4;        // f group
    const int fmt = g_mask_fmt;
    const int b   = bh >> 4;

    const float4* kg = (const float4*)(kk + (size_t)bh * SS * DD);
    const float4* vg = (const float4*)(vv + (size_t)bh * SS * DD);

    ull acc[4][2];
#pragma unroll
    for (int a = 0; a < 4; a++) { acc[a][0] = 0ull; acc[a][1] = 0ull; }
    // loader-side ksum for d = 4*(tid&15) .. +3 (c4 = tid&15 on loads)
    float4 ks4 = make_float4(0.f, 0.f, 0.f, 0.f);

    float4 kr[2], vr[2];

    // prefetch stage 0
#pragma unroll
    for (int it = 0; it < 2; it++) {
        int vi = it * 256 + tid;
        int sl = vi >> 4, c4 = vi & 15;
        float valid = get_valid(mask, fmt, b * SS + s0 + sl);
        float4 k4 = kg[(size_t)(s0 + sl) * 16 + c4];
        vr[it] = vg[(size_t)(s0 + sl) * 16 + c4];
        k4.x = fmap(k4.x) * valid;
        k4.y = fmap(k4.y) * valid;
        k4.z = fmap(k4.z) * valid;
        k4.w = fmap(k4.w) * valid;
        kr[it] = k4;
        ks4.x += k4.x; ks4.y += k4.y; ks4.z += k4.z; ks4.w += k4.w;
    }

    for (int st = 0; st < 16; st++) {
        const int bufi = st & 1;
        // store current stage regs -> smem
#pragma unroll
        for (int it = 0; it < 2; it++) {
            ((float4*)ksh[bufi])[it * 256 + tid] = kr[it];
            ((float4*)vsh[bufi])[it * 256 + tid] = vr[it];
        }
        __syncthreads();

        // prefetch next stage (overlaps with compute below)
        if (st < 15) {
            const int sbase = s0 + (st + 1) * 32;
#pragma unroll
            for (int it = 0; it < 2; it++) {
                int vi = it * 256 + tid;
                int sl = vi >> 4, c4 = vi & 15;
                float valid = get_valid(mask, fmt, b * SS + sbase + sl);
                float4 k4 = kg[(size_t)(sbase + sl) * 16 + c4];
                vr[it] = vg[(size_t)(sbase + sl) * 16 + c4];
                k4.x = fmap(k4.x) * valid;
                k4.y = fmap(k4.y) * valid;
                k4.z = fmap(k4.z) * valid;
                k4.w = fmap(k4.w) * valid;
                kr[it] = k4;
                ks4.x += k4.x; ks4.y += k4.y; ks4.z += k4.z; ks4.w += k4.w;
            }
        }

        // compute 32 tokens from buf — pure LDS + pack + FMA2
        const float* kb = ksh[bufi];
        const float* vb = vsh[bufi];
#pragma unroll 8
        for (int m = 0; m < 32; m++) {
            float4 kd = *(const float4*)(kb + m * 64 + 4 * i);
            ulonglong2 vd = *(const ulonglong2*)(vb + m * 64 + 4 * j);
            ull p;
            p = packf2(kd.x, kd.x); fma2(acc[0][0], p, vd.x); fma2(acc[0][1], p, vd.y);
            p = packf2(kd.y, kd.y); fma2(acc[1][0], p, vd.x); fma2(acc[1][1], p, vd.y);
            p = packf2(kd.z, kd.z); fma2(acc[2][0], p, vd.x); fma2(acc[2][1], p, vd.y);
            p = packf2(kd.w, kd.w); fma2(acc[3][0], p, vd.x); fma2(acc[3][1], p, vd.y);
        }
        // no trailing sync: next stage writes the other buffer, and passing
        // the next store-sync implies all warps finished this compute.
    }

    // store this block's partial kv tile (disjoint per thread — plain stores)
    float* dst = g_kvp + (size_t)(blockIdx.x * NBH + bh) * DD * DD;
#pragma unroll
    for (int a = 0; a < 4; a++) {
        float2 lo = unpackf2(acc[a][0]);
        float2 hi = unpackf2(acc[a][1]);
        float4 o = make_float4(lo.x, lo.y, hi.x, hi.y);
        *(float4*)(dst + (4 * i + a) * 64 + 4 * j) = o;
    }

    // ksum reduce: lanes l and l^16 hold the same c4 column group
    ks4.x += __shfl_xor_sync(0xffffffffu, ks4.x, 16);
    ks4.y += __shfl_xor_sync(0xffffffffu, ks4.y, 16);
    ks4.z += __shfl_xor_sync(0xffffffffu, ks4.z, 16);
    ks4.w += __shfl_xor_sync(0xffffffffu, ks4.w, 16);
    const int lane = tid & 31, w = tid >> 5;
    __syncthreads();     // done with ksh/vsh reads
    if (lane < 16)
        *(float4*)(ksbuf + (w * 16 + lane) * 4) = ks4;
    __syncthreads();
    if (tid < 64) {
        const int c4 = tid & 15, comp = tid >> 4;
        float s = 0.f;
#pragma unroll
        for (int ww = 0; ww < 8; ww++)
            s += ksbuf[(ww * 16 + c4) * 4 + comp];
        atomicAdd(&g_ksum[bh * DD + 4 * c4 + comp], s);
    }
}

// ---------- Pass 2 ---------- (R3/R6 winner, verbatim)
// grid (32, 64), 128 threads, 128 tokens/block, thread tile 8t x 8f.
__global__ void __launch_bounds__(128)
pass2_kernel(const float* __restrict__ qq, float* __restrict__ out) {
    __shared__ float qsh[64 * 128];   // [d][t]
    __shared__ float kvsh[64 * 64];   // [d][f]
    __shared__ float kss[64];
    __shared__ float zsh[128];

    const int bh  = blockIdx.y;
    const int t0  = blockIdx.x * 128;
    const int tid = threadIdx.x;

    const float4* kvg = (const float4*)(g_kv + bh * DD * DD);
#pragma unroll
    for (int it = 0; it < 8; it++)
        ((float4*)kvsh)[it * 128 + tid] = kvg[it * 128 + tid];
    if (tid < 16)
        ((float4*)kss)[tid] = ((const float4*)(g_ksum + bh * DD))[tid];

    const float4* qg = (const float4*)(qq + (size_t)bh * SS * DD + (size_t)t0 * DD);
    float4 qr[16];
#pragma unroll
    for (int c = 0; c < 16; c++) {
        float4 x = qg[tid * 16 + c];
        x.x = fmap(x.x); x.y = fmap(x.y); x.z = fmap(x.z); x.w = fmap(x.w);
        qr[c] = x;
    }
    __syncthreads();

    float z = EPS;
#pragma unroll
    for (int c = 0; c < 16; c++) {
        z += qr[c].x * kss[4 * c] + qr[c].y * kss[4 * c + 1]
           + qr[c].z * kss[4 * c + 2] + qr[c].w * kss[4 * c + 3];
    }
    zsh[tid] = 1.0f / z;

#pragma unroll
    for (int c = 0; c < 16; c++) {
        qsh[(4 * c + 0) * 128 + tid] = qr[c].x;
        qsh[(4 * c + 1) * 128 + tid] = qr[c].y;
        qsh[(4 * c + 2) * 128 + tid] = qr[c].z;
        qsh[(4 * c + 3) * 128 + tid] = qr[c].w;
    }
    __syncthreads();

    const int ty = tid >> 3;   // 0..15
    const int tx = tid & 7;    // 0..7

    ull acc[8][4];
#pragma unroll
    for (int r = 0; r < 8; r++)
#pragma unroll
        for (int p = 0; p < 4; p++) acc[r][p] = 0ull;

#pragma unroll 4
    for (int d = 0; d < 64; d++) {
        float4 qa = *(const float4*)(qsh + d * 128 + 4 * ty);
        float4 qb = *(const float4*)(qsh + d * 128 + 64 + 4 * ty);
        ulonglong2 va = *(const ulonglong2*)(kvsh + d * 64 + 4 * tx);
        ulonglong2 vb = *(const ulonglong2*)(kvsh + d * 64 + 32 + 4 * tx);
        float qs[8] = {qa.x, qa.y, qa.z, qa.w, qb.x, qb.y, qb.z, qb.w};
#pragma unroll
        for (int r = 0; r < 8; r++) {
            ull qp = packf2(qs[r], qs[r]);
            fma2(acc[r][0], qp, va.x);
            fma2(acc[r][1], qp, va.y);
            fma2(acc[r][2], qp, vb.x);
            fma2(acc[r][3], qp, vb.y);
        }
    }

#pragma unroll
    for (int r = 0; r < 8; r++) {
        const int t = (r < 4) ? (4 * ty + r) : (64 + 4 * ty + r - 4);
        const float invz = zsh[t];
        float* og = out + (size_t)bh * SS * DD + (size_t)(t0 + t) * DD;
        float2 a0 = unpackf2(acc[r][0]);
        float2 a1 = unpackf2(acc[r][1]);
        float2 a2 = unpackf2(acc[r][2]);
        float2 a3 = unpackf2(acc[r][3]);
        float4 o0 = make_float4(a0.x * invz, a0.y * invz, a1.x * invz, a1.y * invz);
        float4 o1 = make_float4(a2.x * invz, a2.y * invz, a3.x * invz, a3.y * invz);
        *(float4*)(og + 4 * tx)      = o0;
        *(float4*)(og + 32 + 4 * tx) = o1;
    }
}

extern "C" void kernel_launch(void* const* d_in, const int* in_sizes, int n_in,
                              void* d_out, int out_size) {
    const float* q = (const float*)d_in[0];
    const float* k = (const float*)d_in[1];
    const float* v = (const float*)d_in[2];
    const void*  m = d_in[3];
    float* out = (float*)d_out;

    zero_kernel<<<16, 256>>>();
    detect_kernel<<<16, 256>>>((const unsigned int*)m);
    pass1_kernel<<<dim3(NCHUNK, NBH), 256>>>(k, v, m);
    reduce_kernel<<<512, 128>>>();
    pass2_kernel<<<dim3(SS / 128, NBH), 128>>>(q, out);
}

// round 12
// speedup vs baseline: 2.0183x; 1.0013x over previous
#include <cuda_runtime.h>

#define BB 4
#define HH 16
#define SS 4096
#define DD 64
#define NBH (BB*HH)
#define NCHUNK 8
#define EPS 1e-6f

__device__ float g_kv[NBH * DD * DD];             // [bh][d][f] (final)
__device__ float g_kvp[NCHUNK * NBH * DD * DD];   // per-chunk partials (8MB)
__device__ float g_ksum[NBH * DD];                // [bh][d]
__device__ int   g_mask_fmt;                      // 0 = 4-byte elems, 1 = 1-byte

typedef unsigned long long ull;

// ---------- helpers ----------
__device__ __forceinline__ float fmap(float x) {
    return x > 0.0f ? x + 1.0f : __expf(x);
}

__device__ __forceinline__ void fma2(ull &acc, ull a, ull b) {
    asm("fma.rn.f32x2 %0, %1, %2, %0;" : "+l"(acc) : "l"(a), "l"(b));
}

__device__ __forceinline__ ull packf2(float x, float y) {
    ull r;
    asm("mov.b64 %0, {%1, %2};" : "=l"(r) : "f"(x), "f"(y));
    return r;
}

__device__ __forceinline__ float2 unpackf2(ull v) {
    float2 r;
    asm("mov.b64 {%0, %1}, %2;" : "=f"(r.x), "=f"(r.y) : "l"(v));
    return r;
}

__device__ __forceinline__ float get_valid(const void* mask, int fmt, int idx) {
    if (fmt) return ((const unsigned char*)mask)[idx] == 0 ? 1.0f : 0.0f;
    return ((const unsigned int*)mask)[idx] == 0u ? 1.0f : 0.0f;
}

// ---------- small kernels ----------
__global__ void zero_kernel() {
    int idx = blockIdx.x * blockDim.x + threadIdx.x;
    if (idx < NBH * DD) g_ksum[idx] = 0.0f;
    if (idx == 0)       g_mask_fmt = 0;
}

__global__ void detect_kernel(const unsigned int* __restrict__ mask) {
    int idx = blockIdx.x * blockDim.x + threadIdx.x;  // 4096 threads
    unsigned int w = mask[idx];
    if (w != 0u && w != 1u && w != 0x3F800000u) atomicOr(&g_mask_fmt, 1);
}

// Sum the NCHUNK partial kv matrices. grid 512 x 128 threads, 1 float4/thread.
__global__ void __launch_bounds__(128)
reduce_kernel() {
    const int gidx = blockIdx.x * 128 + threadIdx.x;   // 0..65535
    const int bh  = gidx >> 10;
    const int pos = gidx & 1023;
    const float4* src = (const float4*)g_kvp;
    float4 s = src[(size_t)bh * 1024 + pos];
#pragma unroll
    for (int c = 1; c < NCHUNK; c++) {
        float4 t = src[(size_t)(c * NBH + bh) * 1024 + pos];
        s.x += t.x; s.y += t.y; s.z += t.z; s.w += t.w;
    }
    ((float4*)(g_kv + bh * DD * DD))[pos] = s;
}

// ---------- Pass 1 ----------
// grid (NCHUNK, 64), 128 threads. Thread (i=tid&15, j=tid>>4) owns the
// DISJOINT tile d=4i..4i+3 x f=8j..8j+7 (16 FMA2/token). 16-token stages,
// double-buffered register prefetch, loader-side ksum.
__global__ void __launch_bounds__(128)
pass1_kernel(const float* __restrict__ kk, const float* __restrict__ vv,
             const void* __restrict__ mask) {
    __shared__ float ksh[2][1024];        // 16 tokens x 64
    __shared__ float vsh[2][1024];
    __shared__ float ksbuf[4 * 16 * 4];   // per-warp ksum partials

    const int bh  = blockIdx.y;
    const int s0  = blockIdx.x * 512;
    const int tid = threadIdx.x;
    const int i   = tid & 15;        // d group: d = 4i..4i+3
    const int j   = tid >> 4;        // f group: f = 8j..8j+7
    const int fmt = g_mask_fmt;
    const int b   = bh >> 4;

    const float4* kg = (const float4*)(kk + (size_t)bh * SS * DD);
    const float4* vg = (const float4*)(vv + (size_t)bh * SS * DD);

    ull acc[4][4];
#pragma unroll
    for (int a = 0; a < 4; a++)
#pragma unroll
        for (int p = 0; p < 4; p++) acc[a][p] = 0ull;
    // loader-side ksum for k-cols 4*(tid&15)..+3 (c4 == i on all loads)
    float4 ks4 = make_float4(0.f, 0.f, 0.f, 0.f);

    float4 kr[2], vr[2];

    // prefetch stage 0 (16 tokens = 256 float4, 2 per thread)
#pragma unroll
    for (int it = 0; it < 2; it++) {
        int vi = it * 128 + tid;
        int sl = vi >> 4, c4 = vi & 15;
        float valid = get_valid(mask, fmt, b * SS + s0 + sl);
        float4 k4 = kg[(size_t)(s0 + sl) * 16 + c4];
        vr[it] = vg[(size_t)(s0 + sl) * 16 + c4];
        k4.x = fmap(k4.x) * valid;
        k4.y = fmap(k4.y) * valid;
        k4.z = fmap(k4.z) * valid;
        k4.w = fmap(k4.w) * valid;
        kr[it] = k4;
        ks4.x += k4.x; ks4.y += k4.y; ks4.z += k4.z; ks4.w += k4.w;
    }

    for (int st = 0; st < 32; st++) {
        const int bufi = st & 1;
        // store current stage regs -> smem
#pragma unroll
        for (int it = 0; it < 2; it++) {
            ((float4*)ksh[bufi])[it * 128 + tid] = kr[it];
            ((float4*)vsh[bufi])[it * 128 + tid] = vr[it];
        }
        __syncthreads();

        // prefetch next stage (overlaps with compute below)
        if (st < 31) {
            const int sbase = s0 + (st + 1) * 16;
#pragma unroll
            for (int it = 0; it < 2; it++) {
                int vi = it * 128 + tid;
                int sl = vi >> 4, c4 = vi & 15;
                float valid = get_valid(mask, fmt, b * SS + sbase + sl);
                float4 k4 = kg[(size_t)(sbase + sl) * 16 + c4];
                vr[it] = vg[(size_t)(sbase + sl) * 16 + c4];
                k4.x = fmap(k4.x) * valid;
                k4.y = fmap(k4.y) * valid;
                k4.z = fmap(k4.z) * valid;
                k4.w = fmap(k4.w) * valid;
                kr[it] = k4;
                ks4.x += k4.x; ks4.y += k4.y; ks4.z += k4.z; ks4.w += k4.w;
            }
        }

        // compute 16 tokens: 3 LDS.128 + 4 packs + 16 FMA2 per token
        const float* kb = ksh[bufi];
        const float* vb = vsh[bufi];
#pragma unroll 8
        for (int m = 0; m < 16; m++) {
            float4 kd = *(const float4*)(kb + m * 64 + 4 * i);
            ulonglong2 va = *(const ulonglong2*)(vb + m * 64 + 8 * j);
            ulonglong2 vc = *(const ulonglong2*)(vb + m * 64 + 8 * j + 4);
            ull p;
            p = packf2(kd.x, kd.x);
            fma2(acc[0][0], p, va.x); fma2(acc[0][1], p, va.y);
            fma2(acc[0][2], p, vc.x); fma2(acc[0][3], p, vc.y);
            p = packf2(kd.y, kd.y);
            fma2(acc[1][0], p, va.x); fma2(acc[1][1], p, va.y);
            fma2(acc[1][2], p, vc.x); fma2(acc[1][3], p, vc.y);
            p = packf2(kd.z, kd.z);
            fma2(acc[2][0], p, va.x); fma2(acc[2][1], p, va.y);
            fma2(acc[2][2], p, vc.x); fma2(acc[2][3], p, vc.y);
            p = packf2(kd.w, kd.w);
            fma2(acc[3][0], p, va.x); fma2(acc[3][1], p, va.y);
            fma2(acc[3][2], p, vc.x); fma2(acc[3][3], p, vc.y);
        }
        // no trailing sync: next iteration's barrier protects the other buffer
    }

    // store this block's partial kv tile (disjoint per thread — plain stores)
    float* dst = g_kvp + (size_t)(blockIdx.x * NBH + bh) * DD * DD;
#pragma unroll
    for (int a = 0; a < 4; a++) {
        float2 u0 = unpackf2(acc[a][0]);
        float2 u1 = unpackf2(acc[a][1]);
        float2 u2 = unpackf2(acc[a][2]);
        float2 u3 = unpackf2(acc[a][3]);
        float* row = dst + (4 * i + a) * 64 + 8 * j;
        *(float4*)(row)     = make_float4(u0.x, u0.y, u1.x, u1.y);
        *(float4*)(row + 4) = make_float4(u2.x, u2.y, u3.x, u3.y);
    }

    // ksum reduce: lanes l and l^16 hold the same c4 column group
    ks4.x += __shfl_xor_sync(0xffffffffu, ks4.x, 16);
    ks4.y += __shfl_xor_sync(0xffffffffu, ks4.y, 16);
    ks4.z += __shfl_xor_sync(0xffffffffu, ks4.z, 16);
    ks4.w += __shfl_xor_sync(0xffffffffu, ks4.w, 16);
    const int lane = tid & 31, w = tid >> 5;
    __syncthreads();     // done with ksh/vsh reads
    if (lane < 16)
        *(float4*)(ksbuf + (w * 16 + lane) * 4) = ks4;
    __syncthreads();
    if (tid < 64) {
        const int c4 = tid & 15, comp = tid >> 4;
        float s = 0.f;
#pragma unroll
        for (int ww = 0; ww < 4; ww++)
            s += ksbuf[(ww * 16 + c4) * 4 + comp];
        atomicAdd(&g_ksum[bh * DD + 4 * c4 + comp], s);
    }
}

// ---------- Pass 2 ---------- (R11 winner, verbatim)
// grid (32, 64), 128 threads, 128 tokens/block, thread tile 8t x 8f.
__global__ void __launch_bounds__(128)
pass2_kernel(const float* __restrict__ qq, float* __restrict__ out) {
    __shared__ float qsh[64 * 128];   // [d][t]
    __shared__ float kvsh[64 * 64];   // [d][f]
    __shared__ float kss[64];
    __shared__ float zsh[128];

    const int bh  = blockIdx.y;
    const int t0  = blockIdx.x * 128;
    const int tid = threadIdx.x;

    const float4* kvg = (const float4*)(g_kv + bh * DD * DD);
#pragma unroll
    for (int it = 0; it < 8; it++)
        ((float4*)kvsh)[it * 128 + tid] = kvg[it * 128 + tid];
    if (tid < 16)
        ((float4*)kss)[tid] = ((const float4*)(g_ksum + bh * DD))[tid];

    const float4* qg = (const float4*)(qq + (size_t)bh * SS * DD + (size_t)t0 * DD);
    float4 qr[16];
#pragma unroll
    for (int c = 0; c < 16; c++) {
        float4 x = qg[tid * 16 + c];
        x.x = fmap(x.x); x.y = fmap(x.y); x.z = fmap(x.z); x.w = fmap(x.w);
        qr[c] = x;
    }
    __syncthreads();

    float z = EPS;
#pragma unroll
    for (int c = 0; c < 16; c++) {
        z += qr[c].x * kss[4 * c] + qr[c].y * kss[4 * c + 1]
           + qr[c].z * kss[4 * c + 2] + qr[c].w * kss[4 * c + 3];
    }
    zsh[tid] = 1.0f / z;

#pragma unroll
    for (int c = 0; c < 16; c++) {
        qsh[(4 * c + 0) * 128 + tid] = qr[c].x;
        qsh[(4 * c + 1) * 128 + tid] = qr[c].y;
        qsh[(4 * c + 2) * 128 + tid] = qr[c].z;
        qsh[(4 * c + 3) * 128 + tid] = qr[c].w;
    }
    __syncthreads();

    const int ty = tid >> 3;   // 0..15
    const int tx = tid & 7;    // 0..7

    ull acc[8][4];
#pragma unroll
    for (int r = 0; r < 8; r++)
#pragma unroll
        for (int p = 0; p < 4; p++) acc[r][p] = 0ull;

#pragma unroll 4
    for (int d = 0; d < 64; d++) {
        float4 qa = *(const float4*)(qsh + d * 128 + 4 * ty);
        float4 qb = *(const float4*)(qsh + d * 128 + 64 + 4 * ty);
        ulonglong2 va = *(const ulonglong2*)(kvsh + d * 64 + 4 * tx);
        ulonglong2 vb = *(const ulonglong2*)(kvsh + d * 64 + 32 + 4 * tx);
        float qs[8] = {qa.x, qa.y, qa.z, qa.w, qb.x, qb.y, qb.z, qb.w};
#pragma unroll
        for (int r = 0; r < 8; r++) {
            ull qp = packf2(qs[r], qs[r]);
            fma2(acc[r][0], qp, va.x);
            fma2(acc[r][1], qp, va.y);
            fma2(acc[r][2], qp, vb.x);
            fma2(acc[r][3], qp, vb.y);
        }
    }

#pragma unroll
    for (int r = 0; r < 8; r++) {
        const int t = (r < 4) ? (4 * ty + r) : (64 + 4 * ty + r - 4);
        const float invz = zsh[t];
        float* og = out + (size_t)bh * SS * DD + (size_t)(t0 + t) * DD;
        float2 a0 = unpackf2(acc[r][0]);
        float2 a1 = unpackf2(acc[r][1]);
        float2 a2 = unpackf2(acc[r][2]);
        float2 a3 = unpackf2(acc[r][3]);
        float4 o0 = make_float4(a0.x * invz, a0.y * invz, a1.x * invz, a1.y * invz);
        float4 o1 = make_float4(a2.x * invz, a2.y * invz, a3.x * invz, a3.y * invz);
        *(float4*)(og + 4 * tx)      = o0;
        *(float4*)(og + 32 + 4 * tx) = o1;
    }
}

extern "C" void kernel_launch(void* const* d_in, const int* in_sizes, int n_in,
                              void* d_out, int out_size) {
    const float* q = (const float*)d_in[0];
    const float* k = (const float*)d_in[1];
    const float* v = (const float*)d_in[2];
    const void*  m = d_in[3];
    float* out = (float*)d_out;

    zero_kernel<<<16, 256>>>();
    detect_kernel<<<16, 256>>>((const unsigned int*)m);
    pass1_kernel<<<dim3(NCHUNK, NBH), 128>>>(k, v, m);
    reduce_kernel<<<512, 128>>>();
    pass2_kernel<<<dim3(SS / 128, NBH), 128>>>(q, out);
}